// round 2
// baseline (speedup 1.0000x reference)
#include <cuda_runtime.h>
#include <cstddef>

// ---------------------------------------------------------------------------
// Problem constants (shapes fixed by the dataset)
// ---------------------------------------------------------------------------
#define NN 50000
#define EE 800000

// ---------------------------------------------------------------------------
// Device-global scratch (no dynamic allocation allowed)
// ---------------------------------------------------------------------------
__device__ float g_bufA[(size_t)NN * 256];
__device__ float g_bufB[(size_t)NN * 256];
__device__ float g_bufC[(size_t)NN * 256];
__device__ float g_b64A[(size_t)NN * 64];
__device__ float g_b64B[(size_t)NN * 64];
__device__ float g_b64C[(size_t)NN * 64];
__device__ float g_b16A[(size_t)NN * 16];
__device__ float g_b16B[(size_t)NN * 16];
__device__ float g_b16C[(size_t)NN * 16];
__device__ float g_als[(size_t)NN * 4];
__device__ float g_ald[(size_t)NN * 4];
__device__ float g_dinv[NN];
__device__ int   g_deg[NN];
__device__ int   g_cur[NN];
__device__ int   g_rowptr[NN + 1];
__device__ int   g_csr[EE];
__device__ float g_s1[256], g_q1[256];
__device__ float g_s2[64],  g_q2[64];
__device__ float g_s3[16],  g_q3[16];
__device__ float g_scale[256], g_shift[256];
__device__ int   g_is64;

__device__ __forceinline__ float lk01(float x) { return x > 0.f ? x : 0.01f * x; }
__device__ __forceinline__ float lk2 (float x) { return x > 0.f ? x : 0.2f  * x; }

// ---------------------------------------------------------------------------
// Edge dtype detection: if buffer is int64 (values < 2^31), every odd int32
// word is 0. If it is int32 node ids, odd words are random nonzero.
// ---------------------------------------------------------------------------
__global__ void k_detect(const int* __restrict__ ei32, int E) {
    __shared__ int acc[32];
    int t = threadIdx.x;
    int o = 0;
    // check odd words across the first 8*32=256 pairs (well inside buffer)
    for (int i = 0; i < 8; i++) {
        int idx = 2 * (t + i * 32) + 1;
        if (idx < 2 * E) o |= ei32[idx];
    }
    acc[t] = o;
    __syncthreads();
    if (t == 0) {
        int r = 0;
        for (int i = 0; i < 32; i++) r |= acc[i];
        g_is64 = (r == 0) ? 1 : 0;
    }
}

__device__ __forceinline__ int edge_src(const void* ei, int E, int e) {
    if (g_is64) return (int)((const long long*)ei)[e];
    return ((const int*)ei)[e];
}
__device__ __forceinline__ int edge_dst(const void* ei, int E, int e) {
    if (g_is64) return (int)((const long long*)ei)[(size_t)E + e];
    return ((const int*)ei)[(size_t)E + e];
}

// ---------------------------------------------------------------------------
// Graph preprocessing
// ---------------------------------------------------------------------------
__global__ void k_zero(int n) {
    int i = blockIdx.x * blockDim.x + threadIdx.x;
    if (i < n)   { g_deg[i] = 0; g_cur[i] = 0; }
    if (i < 256) { g_s1[i] = 0.f; g_q1[i] = 0.f; }
    if (i < 64)  { g_s2[i] = 0.f; g_q2[i] = 0.f; }
    if (i < 16)  { g_s3[i] = 0.f; g_q3[i] = 0.f; }
}

__global__ void k_count(const void* __restrict__ ei, int E, int n) {
    int e = blockIdx.x * blockDim.x + threadIdx.x;
    if (e >= E) return;
    int d = edge_dst(ei, E, e);
    if ((unsigned)d < (unsigned)n) atomicAdd(&g_deg[d], 1);
}

__global__ void k_dinv(int n) {
    int i = blockIdx.x * blockDim.x + threadIdx.x;
    if (i < n) g_dinv[i] = rsqrtf((float)g_deg[i] + 1.0f);
}

// Single-block exclusive scan of g_deg -> g_rowptr
__global__ void k_scan(int n) {
    __shared__ int sh[1024];
    int t = threadIdx.x;
    int chunk = (n + 1023) / 1024;
    int b = t * chunk;
    int e = b + chunk; if (e > n) e = n;
    int sum = 0;
    for (int i = b; i < e; i++) sum += g_deg[i];
    sh[t] = sum;
    __syncthreads();
    for (int off = 1; off < 1024; off <<= 1) {
        int v = (t >= off) ? sh[t - off] : 0;
        __syncthreads();
        sh[t] += v;
        __syncthreads();
    }
    int excl = (t == 0) ? 0 : sh[t - 1];
    for (int i = b; i < e; i++) { g_rowptr[i] = excl; excl += g_deg[i]; }
    if (t == 1023) g_rowptr[n] = sh[1023];
}

__global__ void k_fill(const void* __restrict__ ei, int E, int n) {
    int e = blockIdx.x * blockDim.x + threadIdx.x;
    if (e >= E) return;
    int src = edge_src(ei, E, e);
    int dst = edge_dst(ei, E, e);
    if ((unsigned)src >= (unsigned)n || (unsigned)dst >= (unsigned)n) return;
    int pos = g_rowptr[dst] + atomicAdd(&g_cur[dst], 1);
    if ((unsigned)pos < (unsigned)EE) g_csr[pos] = src;
}

// ---------------------------------------------------------------------------
// SGEMM: C[M,Nc] = A[M,K] @ B[K,Nc] (+ bias). 128x128 tile, 8x8 micro, BK=8.
// K % 8 == 0, Nc % 8 == 0 (true here: K,Nc in {16,64,256})
// ---------------------------------------------------------------------------
__global__ void __launch_bounds__(256) k_gemm(
    const float* __restrict__ A, const float* __restrict__ B,
    const float* __restrict__ bias, float* __restrict__ C,
    int M, int K, int Nc)
{
    __shared__ float As[8][132];
    __shared__ float Bs[8][128];
    int tid = threadIdx.x;
    int tx = tid & 15, ty = tid >> 4;
    int row0 = blockIdx.y * 128, col0 = blockIdx.x * 128;

    int arow = tid >> 1;           // 0..127
    int ak   = (tid & 1) * 4;      // 0 or 4
    int brow = tid >> 5;           // 0..7
    int bc   = (tid & 31) * 4;     // 0..124

    bool aok = (row0 + arow) < M;
    bool bok = (col0 + bc + 3) < Nc;

    float acc[8][8];
#pragma unroll
    for (int i = 0; i < 8; i++)
#pragma unroll
        for (int j = 0; j < 8; j++) acc[i][j] = 0.f;

    for (int k0 = 0; k0 < K; k0 += 8) {
        float4 av = make_float4(0.f, 0.f, 0.f, 0.f);
        if (aok) av = *(const float4*)(A + (size_t)(row0 + arow) * K + k0 + ak);
        As[ak + 0][arow] = av.x;
        As[ak + 1][arow] = av.y;
        As[ak + 2][arow] = av.z;
        As[ak + 3][arow] = av.w;
        float4 bv = make_float4(0.f, 0.f, 0.f, 0.f);
        if (bok) bv = *(const float4*)(B + (size_t)(k0 + brow) * Nc + col0 + bc);
        *(float4*)&Bs[brow][bc] = bv;
        __syncthreads();
#pragma unroll
        for (int k = 0; k < 8; k++) {
            float4 a0 = *(const float4*)&As[k][ty * 8];
            float4 a1 = *(const float4*)&As[k][ty * 8 + 4];
            float4 b0 = *(const float4*)&Bs[k][tx * 8];
            float4 b1 = *(const float4*)&Bs[k][tx * 8 + 4];
            float a[8] = {a0.x, a0.y, a0.z, a0.w, a1.x, a1.y, a1.z, a1.w};
            float b[8] = {b0.x, b0.y, b0.z, b0.w, b1.x, b1.y, b1.z, b1.w};
#pragma unroll
            for (int i = 0; i < 8; i++)
#pragma unroll
                for (int j = 0; j < 8; j++) acc[i][j] += a[i] * b[j];
        }
        __syncthreads();
    }

    bool cok = (col0 + tx * 8 + 7) < Nc;   // Nc % 8 == 0: all-or-nothing per thread
    float bvv[8];
#pragma unroll
    for (int j = 0; j < 8; j++)
        bvv[j] = (bias && cok) ? bias[col0 + tx * 8 + j] : 0.f;

    if (cok) {
#pragma unroll
        for (int i = 0; i < 8; i++) {
            int r = row0 + ty * 8 + i;
            if (r < M) {
                float* cp = C + (size_t)r * Nc + col0 + tx * 8;
                float4 o0 = make_float4(acc[i][0] + bvv[0], acc[i][1] + bvv[1],
                                        acc[i][2] + bvv[2], acc[i][3] + bvv[3]);
                float4 o1 = make_float4(acc[i][4] + bvv[4], acc[i][5] + bvv[5],
                                        acc[i][6] + bvv[6], acc[i][7] + bvv[7]);
                *(float4*)cp = o0;
                *(float4*)(cp + 4) = o1;
            }
        }
    }
}

// ---------------------------------------------------------------------------
// GCN gather: out[n] = sum_{s->n} dinv[s]*dinv[n]*h[s] + dinv[n]^2*h[n] + b
// C=256: one warp per node, 8 floats/lane.
// ---------------------------------------------------------------------------
__global__ void k_gcn_gather256(const float* __restrict__ h, const float* __restrict__ bias,
                                float* __restrict__ out, int n)
{
    int gt = blockIdx.x * blockDim.x + threadIdx.x;
    int nd = gt >> 5, lane = gt & 31;
    if (nd >= n) return;
    int f0 = lane * 8;
    float din = g_dinv[nd];
    float sw = din * din;
    const float4* hp = (const float4*)(h + (size_t)nd * 256 + f0);
    float4 v0 = hp[0], v1 = hp[1];
    const float4* bp = (const float4*)(bias + f0);
    float4 b0 = bp[0], b1 = bp[1];
    float4 a0, a1;
    a0.x = v0.x * sw + b0.x; a0.y = v0.y * sw + b0.y;
    a0.z = v0.z * sw + b0.z; a0.w = v0.w * sw + b0.w;
    a1.x = v1.x * sw + b1.x; a1.y = v1.y * sw + b1.y;
    a1.z = v1.z * sw + b1.z; a1.w = v1.w * sw + b1.w;
    int e = g_rowptr[nd], end = g_rowptr[nd + 1];
    for (; e < end; e++) {
        int s = g_csr[e];
        float wg = g_dinv[s] * din;
        const float4* sp = (const float4*)(h + (size_t)s * 256 + f0);
        float4 u0 = sp[0], u1 = sp[1];
        a0.x += wg * u0.x; a0.y += wg * u0.y; a0.z += wg * u0.z; a0.w += wg * u0.w;
        a1.x += wg * u1.x; a1.y += wg * u1.y; a1.z += wg * u1.z; a1.w += wg * u1.w;
    }
    float4* op = (float4*)(out + (size_t)nd * 256 + f0);
    op[0] = a0; op[1] = a1;
}

// C in {16,64}: C/4 threads per node, one float4 each.
template <int C>
__global__ void k_gcn_gather(const float* __restrict__ h, const float* __restrict__ bias,
                             float* __restrict__ out, int n)
{
    const int G = C / 4;
    int gt = blockIdx.x * blockDim.x + threadIdx.x;
    int nd = gt / G, sub = gt % G;
    if (nd >= n) return;
    int f0 = sub * 4;
    float din = g_dinv[nd];
    float sw = din * din;
    float4 v = *(const float4*)(h + (size_t)nd * C + f0);
    float4 b = *(const float4*)(bias + f0);
    float4 a;
    a.x = v.x * sw + b.x; a.y = v.y * sw + b.y;
    a.z = v.z * sw + b.z; a.w = v.w * sw + b.w;
    int e = g_rowptr[nd], end = g_rowptr[nd + 1];
    for (; e < end; e++) {
        int s = g_csr[e];
        float wg = g_dinv[s] * din;
        float4 u = *(const float4*)(h + (size_t)s * C + f0);
        a.x += wg * u.x; a.y += wg * u.y; a.z += wg * u.z; a.w += wg * u.w;
    }
    *(float4*)(out + (size_t)nd * C + f0) = a;
}

// ---------------------------------------------------------------------------
// GAT attention logits: al_s[n,h] = <hg[n,h,:], a_s[h,:]>, same for a_d.
// ---------------------------------------------------------------------------
__global__ void k_al(const float* __restrict__ hg, const float* __restrict__ a_s,
                     const float* __restrict__ a_d, int n)
{
    int gt = blockIdx.x * blockDim.x + threadIdx.x;
    int w = gt >> 5, lane = gt & 31;
    if (w >= n) return;
    float s0 = 0.f, s1 = 0.f, s2 = 0.f, s3 = 0.f;
    float d0 = 0.f, d1 = 0.f, d2 = 0.f, d3 = 0.f;
#pragma unroll
    for (int j = 0; j < 2; j++) {
        int f = lane * 4 + j * 128;
        float4 v  = *(const float4*)(hg + (size_t)w * 256 + f);
        float4 as = *(const float4*)(a_s + f);
        float4 ad = *(const float4*)(a_d + f);
        float ps = v.x * as.x + v.y * as.y + v.z * as.z + v.w * as.w;
        float pd = v.x * ad.x + v.y * ad.y + v.z * ad.z + v.w * ad.w;
        bool hi = (lane & 16) != 0;
        if (j == 0) { if (hi) { s1 += ps; d1 += pd; } else { s0 += ps; d0 += pd; } }
        else        { if (hi) { s3 += ps; d3 += pd; } else { s2 += ps; d2 += pd; } }
    }
#pragma unroll
    for (int off = 16; off >= 1; off >>= 1) {
        s0 += __shfl_xor_sync(0xffffffffu, s0, off);
        s1 += __shfl_xor_sync(0xffffffffu, s1, off);
        s2 += __shfl_xor_sync(0xffffffffu, s2, off);
        s3 += __shfl_xor_sync(0xffffffffu, s3, off);
        d0 += __shfl_xor_sync(0xffffffffu, d0, off);
        d1 += __shfl_xor_sync(0xffffffffu, d1, off);
        d2 += __shfl_xor_sync(0xffffffffu, d2, off);
        d3 += __shfl_xor_sync(0xffffffffu, d3, off);
    }
    if (lane == 0) {
        *(float4*)(g_als + 4 * (size_t)w) = make_float4(s0, s1, s2, s3);
        *(float4*)(g_ald + 4 * (size_t)w) = make_float4(d0, d1, d2, d3);
    }
}

// GAT fused softmax-aggregate: one warp per node, two passes over in-edges.
__global__ void k_gat(const float* __restrict__ hg, const float* __restrict__ bg,
                      float* __restrict__ out, int n)
{
    int gt = blockIdx.x * blockDim.x + threadIdx.x;
    int w = gt >> 5, lane = gt & 31;
    if (w >= n) return;
    float4 ad = *(const float4*)(g_ald + 4 * (size_t)w);
    float4 sf = *(const float4*)(g_als + 4 * (size_t)w);
    float e0 = lk2(sf.x + ad.x), e1 = lk2(sf.y + ad.y);
    float e2 = lk2(sf.z + ad.z), e3 = lk2(sf.w + ad.w);
    float m0 = e0, m1 = e1, m2 = e2, m3 = e3;
    int beg = g_rowptr[w], end = g_rowptr[w + 1];
    for (int e = beg; e < end; e++) {
        int s = g_csr[e];
        float4 a = *(const float4*)(g_als + 4 * (size_t)s);
        m0 = fmaxf(m0, lk2(a.x + ad.x));
        m1 = fmaxf(m1, lk2(a.y + ad.y));
        m2 = fmaxf(m2, lk2(a.z + ad.z));
        m3 = fmaxf(m3, lk2(a.w + ad.w));
    }
    float den0 = __expf(e0 - m0), den1 = __expf(e1 - m1);
    float den2 = __expf(e2 - m2), den3 = __expf(e3 - m3);
    int f0 = lane * 8;
    int head = lane >> 3;
    float wself = head == 0 ? den0 : head == 1 ? den1 : head == 2 ? den2 : den3;
    const float4* hp = (const float4*)(hg + (size_t)w * 256 + f0);
    float4 v0 = hp[0], v1 = hp[1];
    float a0 = wself * v0.x, a1 = wself * v0.y, a2 = wself * v0.z, a3 = wself * v0.w;
    float a4 = wself * v1.x, a5 = wself * v1.y, a6 = wself * v1.z, a7 = wself * v1.w;
    for (int e = beg; e < end; e++) {
        int s = g_csr[e];
        float4 a = *(const float4*)(g_als + 4 * (size_t)s);
        float w0 = __expf(lk2(a.x + ad.x) - m0);
        float w1 = __expf(lk2(a.y + ad.y) - m1);
        float w2 = __expf(lk2(a.z + ad.z) - m2);
        float w3 = __expf(lk2(a.w + ad.w) - m3);
        den0 += w0; den1 += w1; den2 += w2; den3 += w3;
        float ws = head == 0 ? w0 : head == 1 ? w1 : head == 2 ? w2 : w3;
        const float4* sp = (const float4*)(hg + (size_t)s * 256 + f0);
        float4 u0 = sp[0], u1 = sp[1];
        a0 += ws * u0.x; a1 += ws * u0.y; a2 += ws * u0.z; a3 += ws * u0.w;
        a4 += ws * u1.x; a5 += ws * u1.y; a6 += ws * u1.z; a7 += ws * u1.w;
    }
    float dsel = head == 0 ? den0 : head == 1 ? den1 : head == 2 ? den2 : den3;
    float sc = 0.25f / dsel;
    a0 *= sc; a1 *= sc; a2 *= sc; a3 *= sc;
    a4 *= sc; a5 *= sc; a6 *= sc; a7 *= sc;
    a0 += __shfl_xor_sync(0xffffffffu, a0, 8);  a0 += __shfl_xor_sync(0xffffffffu, a0, 16);
    a1 += __shfl_xor_sync(0xffffffffu, a1, 8);  a1 += __shfl_xor_sync(0xffffffffu, a1, 16);
    a2 += __shfl_xor_sync(0xffffffffu, a2, 8);  a2 += __shfl_xor_sync(0xffffffffu, a2, 16);
    a3 += __shfl_xor_sync(0xffffffffu, a3, 8);  a3 += __shfl_xor_sync(0xffffffffu, a3, 16);
    a4 += __shfl_xor_sync(0xffffffffu, a4, 8);  a4 += __shfl_xor_sync(0xffffffffu, a4, 16);
    a5 += __shfl_xor_sync(0xffffffffu, a5, 8);  a5 += __shfl_xor_sync(0xffffffffu, a5, 16);
    a6 += __shfl_xor_sync(0xffffffffu, a6, 8);  a6 += __shfl_xor_sync(0xffffffffu, a6, 16);
    a7 += __shfl_xor_sync(0xffffffffu, a7, 8);  a7 += __shfl_xor_sync(0xffffffffu, a7, 16);
    if (lane < 8) {
        const float4* bp = (const float4*)(bg + lane * 8);
        float4 b0 = bp[0], b1 = bp[1];
        float4 o0 = make_float4(a0 + b0.x, a1 + b0.y, a2 + b0.z, a3 + b0.w);
        float4 o1 = make_float4(a4 + b1.x, a5 + b1.y, a6 + b1.z, a7 + b1.w);
        float4* op = (float4*)(out + (size_t)w * 64 + lane * 8);
        op[0] = o0; op[1] = o1;
    }
}

// ---------------------------------------------------------------------------
// BatchNorm: stats / finalize / apply(+leaky+residual)
// ---------------------------------------------------------------------------
template <int C>
__global__ void k_bnstats(const float* __restrict__ x, float* __restrict__ gsum,
                          float* __restrict__ gsq, int n)
{
    __shared__ float ss[256], qq[256];
    int tid = threadIdx.x;
    const int R = 256 / C;
    int c = tid % C, r0 = tid / C;
    float s = 0.f, q = 0.f;
    for (int r = blockIdx.x * R + r0; r < n; r += gridDim.x * R) {
        float v = x[(size_t)r * C + c];
        s += v; q += v * v;
    }
    ss[tid] = s; qq[tid] = q;
    __syncthreads();
#pragma unroll
    for (int off = 128; off >= C; off >>= 1) {
        if (tid < off) { ss[tid] += ss[tid + off]; qq[tid] += qq[tid + off]; }
        __syncthreads();
    }
    if (tid < C) {
        atomicAdd(&gsum[tid], ss[tid]);
        atomicAdd(&gsq[tid],  qq[tid]);
    }
}

template <int C>
__global__ void k_bnfin(const float* __restrict__ gsum, const float* __restrict__ gsq,
                        const float* __restrict__ g, const float* __restrict__ be, int n)
{
    int c = threadIdx.x;
    if (c >= C) return;
    float inv = 1.0f / (float)n;
    float mu = gsum[c] * inv;
    float var = gsq[c] * inv - mu * mu;
    float sc = g[c] * rsqrtf(var + 1e-5f);
    g_scale[c] = sc;
    g_shift[c] = be[c] - mu * sc;
}

template <int C>
__global__ void k_apply(const float* __restrict__ x, const float* __restrict__ res,
                        float* __restrict__ out, int n)
{
    int i = blockIdx.x * blockDim.x + threadIdx.x;   // float4 index
    int total = n * (C / 4);
    if (i >= total) return;
    int c4 = i % (C / 4);
    float4 sc = *(const float4*)(g_scale + c4 * 4);
    float4 sh = *(const float4*)(g_shift + c4 * 4);
    float4 v = ((const float4*)x)[i];
    float4 r = ((const float4*)res)[i];
    float4 o;
    o.x = lk01(v.x * sc.x + sh.x) + r.x;
    o.y = lk01(v.y * sc.y + sh.y) + r.y;
    o.z = lk01(v.z * sc.z + sh.z) + r.z;
    o.w = lk01(v.w * sc.w + sh.w) + r.w;
    ((float4*)out)[i] = o;
}

// ---------------------------------------------------------------------------
// Launcher
// ---------------------------------------------------------------------------
extern "C" void kernel_launch(void* const* d_in, const int* in_sizes, int n_in,
                              void* d_out, int out_size)
{
    const float* x     = (const float*)d_in[0];
    const void*  ei    = d_in[1];
    const float* W1    = (const float*)d_in[2];
    const float* b1    = (const float*)d_in[3];
    const float* g1    = (const float*)d_in[4];
    const float* be1   = (const float*)d_in[5];
    const float* Wg    = (const float*)d_in[6];
    const float* a_src = (const float*)d_in[7];
    const float* a_dst = (const float*)d_in[8];
    const float* bg    = (const float*)d_in[9];
    const float* g2    = (const float*)d_in[10];
    const float* be2   = (const float*)d_in[11];
    const float* W3    = (const float*)d_in[12];
    const float* b3    = (const float*)d_in[13];
    const float* g3    = (const float*)d_in[14];
    const float* be3   = (const float*)d_in[15];
    const float* W4    = (const float*)d_in[16];
    const float* b4    = (const float*)d_in[17];
    const float* r1W   = (const float*)d_in[18];
    const float* r1b   = (const float*)d_in[19];
    const float* r2W   = (const float*)d_in[20];
    const float* r2b   = (const float*)d_in[21];
    const float* r3W   = (const float*)d_in[22];
    const float* r3b   = (const float*)d_in[23];
    const float* pW    = (const float*)d_in[24];
    const float* pb    = (const float*)d_in[25];

    int n = in_sizes[0] / 256;
    int E = in_sizes[1] / 2;
    if (E > EE) E = EE;

    float *pA, *pB, *pC, *p64A, *p64B, *p64C, *p16A, *p16B, *p16C;
    float *ps1, *pq1, *ps2, *pq2, *ps3, *pq3;
    cudaGetSymbolAddress((void**)&pA,   g_bufA);
    cudaGetSymbolAddress((void**)&pB,   g_bufB);
    cudaGetSymbolAddress((void**)&pC,   g_bufC);
    cudaGetSymbolAddress((void**)&p64A, g_b64A);
    cudaGetSymbolAddress((void**)&p64B, g_b64B);
    cudaGetSymbolAddress((void**)&p64C, g_b64C);
    cudaGetSymbolAddress((void**)&p16A, g_b16A);
    cudaGetSymbolAddress((void**)&p16B, g_b16B);
    cudaGetSymbolAddress((void**)&p16C, g_b16C);
    cudaGetSymbolAddress((void**)&ps1, g_s1);
    cudaGetSymbolAddress((void**)&pq1, g_q1);
    cudaGetSymbolAddress((void**)&ps2, g_s2);
    cudaGetSymbolAddress((void**)&pq2, g_q2);
    cudaGetSymbolAddress((void**)&ps3, g_s3);
    cudaGetSymbolAddress((void**)&pq3, g_q3);

    float* outp = (float*)d_out;

    // --- graph preprocessing: CSR by dst ---
    k_detect<<<1, 32>>>((const int*)ei, E);
    k_zero  <<<(n + 255) / 256, 256>>>(n);
    k_count <<<(E + 255) / 256, 256>>>(ei, E, n);
    k_dinv  <<<(n + 255) / 256, 256>>>(n);
    k_scan  <<<1, 1024>>>(n);
    k_fill  <<<(E + 255) / 256, 256>>>(ei, E, n);

    dim3 gbig(2, (n + 127) / 128);   // Nc = 256
    dim3 gmed(1, (n + 127) / 128);   // Nc <= 128

    // --- layer 1: GCN(256->256) + BN + leaky + residual ---
    k_gemm<<<gbig, 256>>>(x, W1, nullptr, pA, n, 256, 256);       // h1 = x @ W1
    k_gemm<<<gbig, 256>>>(x, r1W, r1b, pB, n, 256, 256);          // r1
    k_gcn_gather256<<<(n * 32 + 255) / 256, 256>>>(pA, b1, pC, n);
    k_bnstats<256><<<512, 256>>>(pC, ps1, pq1, n);
    k_bnfin<256><<<1, 256>>>(ps1, pq1, g1, be1, n);
    k_apply<256><<<(n * 64 + 255) / 256, 256>>>(pC, pB, pC, n);   // x2 in pC

    // --- layer 2: GAT(256->64, 4 heads, mean) + BN + leaky + residual ---
    k_gemm<<<gbig, 256>>>(pC, Wg, nullptr, pA, n, 256, 256);      // hg = x2 @ Wg
    k_gemm<<<gmed, 256>>>(pC, r2W, r2b, p64B, n, 256, 64);        // r2
    k_al <<<(n * 32 + 255) / 256, 256>>>(pA, a_src, a_dst, n);
    k_gat<<<(n * 32 + 255) / 256, 256>>>(pA, bg, p64A, n);
    k_bnstats<64><<<512, 256>>>(p64A, ps2, pq2, n);
    k_bnfin<64><<<1, 64>>>(ps2, pq2, g2, be2, n);
    k_apply<64><<<(n * 16 + 255) / 256, 256>>>(p64A, p64B, p64C, n);  // x3

    // --- layer 3: GCN(64->16) + BN + leaky + residual ---
    k_gemm<<<gmed, 256>>>(p64C, W3, nullptr, p16A, n, 64, 16);
    k_gcn_gather<16><<<(n * 4 + 255) / 256, 256>>>(p16A, b3, p16B, n);
    k_gemm<<<gmed, 256>>>(p64C, r3W, r3b, p16C, n, 64, 16);
    k_bnstats<16><<<512, 256>>>(p16B, ps3, pq3, n);
    k_bnfin<16><<<1, 16>>>(ps3, pq3, g3, be3, n);
    k_apply<16><<<(n * 4 + 255) / 256, 256>>>(p16B, p16C, p16A, n);   // x4

    // --- layer 4: GCN(16->64), then final projection ---
    k_gemm<<<gmed, 256>>>(p16A, W4, nullptr, p64A, n, 16, 64);
    k_gcn_gather<64><<<(n * 16 + 255) / 256, 256>>>(p64A, b4, p64B, n);
    k_gemm<<<gmed, 256>>>(p64B, pW, pb, outp, n, 64, 64);
}